// round 16
// baseline (speedup 1.0000x reference)
#include <cuda_runtime.h>
#include <math.h>

// Problem constants (fixed shapes)
#define NB 4
#define HB 512
#define WB 512
#define NPIX (NB * HB * WB)   // 1,048,576 pixels

// 1/(float)1e-4 rounds to exactly 10000.0f: FMUL instead of div.rn costs
// 4.8e-8 relative in the exp argument -> ~5e-6 in the weight.
#define INV_GAMMA_F 10000.0f
#define INV_SIGMA_F 10000.0f
// DELTA = exp(1e-10/1e-4)*1e-10 computed in float64 -> float32
#define DELTA_F 1.0000010000005e-10f

// Accumulator: per (n, y, x) -> {sum r*w, sum g*w, sum b*w, sum w} (16 MB).
// Zeroed each call by the copy-engine memset node (NOT by SM stores — SM
// zero-writeback dirties 16 MB of L2 and regressed 2x when tried).
__device__ float4 g_accum[NB * HB * WB];

// Streaming loads (evict-first in L2): single-use input data must not
// displace the L2-resident accumulator that the scatter atomics hammer.
__device__ __forceinline__ float ldcs(const float* p) { return __ldcs(p); }
__device__ __forceinline__ int   ldcs(const int* p)   { return __ldcs(p); }

// One (pixel, k) pair per lane; quad-wide shuffles do the K-reduction.
// Scatter phase: the surviving lane's payload is redistributed across its
// quad so each lane issues ONE red.v4 for one bilinear corner.
__global__ __launch_bounds__(256) void splat_kernel(
    const int*   __restrict__ p2f,     // [N,H,W,K]
    const float* __restrict__ bary,    // [N,H,W,K,3]
    const float* __restrict__ dists,   // [N,H,W,K]
    const float* __restrict__ zbuf,    // [N,H,W,K]
    const float* __restrict__ images,  // [N,H,W,C]
    const float* __restrict__ fuv)     // [F,3,2]
{
    int t = blockIdx.x * blockDim.x + threadIdx.x;   // [0, 4*NPIX), exact grid
    int idx = t >> 2;                                // pixel
    int w = idx & (WB - 1);
    int h = (idx >> 9) & (HB - 1);
    int n = idx >> 18;

    // Coalesced per-lane loads (front-batched for MLP), streaming-hinted.
    int   fk = ldcs(p2f + t);
    float zk = ldcs(zbuf + t);
    float dk = ldcs(dists + t);
    const float* bp = bary + (size_t)t * 3;
    float b0 = ldcs(bp + 0);
    float b1 = ldcs(bp + 1);
    float b2 = ldcs(bp + 2);
    // RGB: all 4 lanes of a quad read the same 12B (L1 broadcast; bitwise
    // identical across the quad — exploited by the scatter loop below).
    float r = ldcs(images + (size_t)idx * 3 + 0);
    float g = ldcs(images + (size_t)idx * 3 + 1);
    float b = ldcs(images + (size_t)idx * 3 + 2);

    const unsigned FULL = 0xffffffffu;
    bool m = (fk >= 0);

    // Exact z_inv for ALL lanes (true division — its rounding is amplified
    // x1e4 by the exp below). Masked lanes contribute 0.0, exactly like the
    // reference's z_inv * mask (valid z_inv is in [0,1], so the quad max
    // matches the reference max including zeros).
    float ze = m ? __fdiv_rn(__fsub_rn(100.0f, zk), 99.0f) : 0.0f;
    float zmax = ze;
    zmax = fmaxf(zmax, __shfl_xor_sync(FULL, zmax, 1));
    zmax = fmaxf(zmax, __shfl_xor_sync(FULL, zmax, 2));

    // Gather gate: __expf underflows to exactly 0 once ze - zmax < -0.0104,
    // so lanes outside the window have wnum == 0 bitwise and need no UVs.
    bool cand = m && (ze >= zmax - 0.0105f);
    float2 u0, u1, u2;
    if (cand) {
        const float2* uvp = (const float2*)(fuv + (size_t)fk * 6);
        u0 = __ldg(uvp + 0);
        u1 = __ldg(uvp + 1);
        u2 = __ldg(uvp + 2);
    }

    // wnum: fast-math weight path (errors here are NOT exp-amplified; the
    // only amplified step, z_inv, stays exact above).
    float wv = 0.0f;
    if (cand) {
        float e = __expf(__fmul_rn(__fsub_rn(ze, zmax), INV_GAMMA_F));
        if (e != 0.0f) {                   // argmax lane: earg==0 -> e==1
            float sarg = __fmul_rn(dk, -INV_SIGMA_F);   // -d/SIGMA
            float pr = __frcp_rn(__fadd_rn(1.0f, __expf(-sarg)));
            wv = __fmul_rn(pr, e);
        }
    }
    // Quad sum (butterfly order: <=1 ulp vs sequential; not exp-amplified).
    float s = wv;
    s = __fadd_rn(s, __shfl_xor_sync(FULL, s, 1));
    s = __fadd_rn(s, __shfl_xor_sync(FULL, s, 2));

    // ---- Per-survivor splat payload (predicated) ----
    bool alive = (wv != 0.0f);
    float wt = 0.f, ptx = 0.f, pty = 0.f;
    int pxy = 0;
    if (alive) {
        wt = __fmul_rn(wv, __frcp_rn(__fadd_rn(s, DELTA_F)));

        // Barycentric-blend UVs. Strict mul/add (no FMA) to match XLA: the
        // floor() bin below is last-ulp sensitive.
        float ux = __fadd_rn(__fadd_rn(__fmul_rn(b0, u0.x), __fmul_rn(b1, u1.x)),
                             __fmul_rn(b2, u2.x));
        float uy = __fadd_rn(__fadd_rn(__fmul_rn(b0, u0.y), __fmul_rn(b1, u1.y)),
                             __fmul_rn(b2, u2.y));

        float gx = __fadd_rn(__fmul_rn(ux, 2.0f), -1.0f);
        float gy = __fadd_rn(__fmul_rn(uy, 2.0f), -1.0f);
        float tgx = __fmul_rn(__fadd_rn(__fmul_rn(gx, 0.5f), 0.5f), 512.0f);
        float tgy = __fmul_rn(__fadd_rn(__fmul_rn(gy, 0.5f), 0.5f), 512.0f);

        // linspace(0,512,512)[i] = i*(512/511); fx = (target - lin) + coord
        const float STEP = 512.0f / 511.0f;
        float fx = __fadd_rn(__fsub_rn(tgx, __fmul_rn((float)w, STEP)), (float)w);
        float fy = __fadd_rn(__fsub_rn(tgy, __fmul_rn((float)h, STEP)), (float)h);

        float x0f = floorf(fx), y0f = floorf(fy);
        int x0 = (int)x0f, y0 = (int)y0f;
        ptx = __fsub_rn(fx, x0f);
        pty = __fsub_rn(fy, y0f);
        // x0,y0 in [-~1, 512]; pack exactly into 16-bit halves (+8 bias).
        pxy = (x0 + 8) | ((y0 + 8) << 16);
    }

    // ---- Corner redistribution: lane k of each quad handles corner k ----
    // Payload is 4 shuffles (wt, tx, ty, packed xy); r,g,b are already
    // quad-uniform so each corner lane recomputes r*wt locally (bitwise
    // identical to computing it at the source lane).
    int lane = threadIdx.x & 31;
    int qbase = lane & ~3;
    int dxc = lane & 1;
    int dyc = (lane >> 1) & 1;
    float4* accum_n = g_accum + ((size_t)n << 18);   // n uniform within quad

    unsigned mask = __ballot_sync(FULL, alive);
    while (mask) {
        unsigned qm = (mask >> qbase) & 0xFu;
        bool act = (qm != 0);
        int src = act ? (qbase + __ffs(qm) - 1) : lane;

        int   sp  = __shfl_sync(FULL, pxy, src);
        float swt = __shfl_sync(FULL, wt,  src);
        float stx = __shfl_sync(FULL, ptx, src);
        float sty = __shfl_sync(FULL, pty, src);

        if (act) {
            int xi = (sp & 0xffff) - 8 + dxc;
            int yi = (sp >> 16) - 8 + dyc;
            if ((unsigned)xi < (unsigned)WB && (unsigned)yi < (unsigned)HB) {
                float wx = dxc ? stx : __fsub_rn(1.0f, stx);
                float wy = dyc ? sty : __fsub_rn(1.0f, sty);
                float wgt = __fmul_rn(wx, wy);
                float4* p = accum_n + ((size_t)yi << 9) + xi;
                asm volatile(
                    "red.global.add.v4.f32 [%0], {%1, %2, %3, %4};"
                    :: "l"(p),
                       "f"(__fmul_rn(__fmul_rn(r, swt), wgt)),
                       "f"(__fmul_rn(__fmul_rn(g, swt), wgt)),
                       "f"(__fmul_rn(__fmul_rn(b, swt), wgt)),
                       "f"(__fmul_rn(swt, wgt))
                    : "memory");
            }
        }
        // Retire the processed survivor in each quad; loop for multi-survivor
        // quads (avg ~1.05 survivors -> usually a single iteration).
        alive = alive && (lane != src);
        mask = __ballot_sync(FULL, alive);
    }
}

// One pixel per thread; coalesced accumulator read (L2-hot thanks to the
// streaming-hinted splat loads), rcp, scalar contiguous stores.
__global__ __launch_bounds__(256) void finalize_kernel(float* __restrict__ out) {
    int idx = blockIdx.x * blockDim.x + threadIdx.x;   // output pixel
    int w = idx & (WB - 1);
    int h = (idx >> 9) & (HB - 1);
    int n = idx >> 18;

    // Flip H: output row h reads accumulator row (H-1-h); same w order.
    const float4* ap = &g_accum[(((size_t)n << 9) + (HB - 1 - h)) * WB + w];
    float4 a = __ldcs(ap);
    float wsum = a.w;
    float rc = __frcp_rn(fmaxf(wsum, 1e-8f));

    float* tex = out + (size_t)idx * 3;
    tex[0] = a.x * rc;
    tex[1] = a.y * rc;
    tex[2] = a.z * rc;

    float* tw = out + (size_t)NPIX * 3 + (size_t)idx * 3;
    tw[0] = wsum;
    tw[1] = wsum;
    tw[2] = wsum;
}

extern "C" void kernel_launch(void* const* d_in, const int* in_sizes, int n_in,
                              void* d_out, int out_size) {
    const int*   p2f    = (const int*)  d_in[0];
    const float* bary   = (const float*)d_in[1];
    const float* dists  = (const float*)d_in[2];
    const float* zbuf   = (const float*)d_in[3];
    const float* images = (const float*)d_in[4];
    const float* fuv    = (const float*)d_in[5];
    float* out = (float*)d_out;

    // Zero the accumulator via a memset node (copy engine; graph-capturable).
    void* accum_ptr = nullptr;
    cudaGetSymbolAddress(&accum_ptr, g_accum);
    cudaMemsetAsync(accum_ptr, 0, (size_t)NPIX * sizeof(float4), 0);

    splat_kernel<<<(NPIX * 4) / 256, 256>>>(p2f, bary, dists, zbuf, images, fuv);
    finalize_kernel<<<NPIX / 256, 256>>>(out);
}

// round 17
// speedup vs baseline: 1.0885x; 1.0885x over previous
#include <cuda_runtime.h>
#include <math.h>

// Problem constants (fixed shapes)
#define NB 4
#define HB 512
#define WB 512
#define NPIX (NB * HB * WB)   // 1,048,576 pixels

// 1/(float)1e-4 rounds to exactly 10000.0f: FMUL instead of div.rn costs
// 4.8e-8 relative in the exp argument -> ~5e-6 in the weight.
#define INV_GAMMA_F 10000.0f
#define INV_SIGMA_F 10000.0f
// DELTA = exp(1e-10/1e-4)*1e-10 computed in float64 -> float32
#define DELTA_F 1.0000010000005e-10f

// Accumulator: per (n, y, x) -> {sum r*w, sum g*w, sum b*w, sum w} (16 MB).
// Zeroed each call by the copy-engine memset node (NOT by SM stores — SM
// zero-writeback dirties 16 MB of L2 and regressed 2x when tried).
__device__ float4 g_accum[NB * HB * WB];

// Streaming loads (evict-first in L2): single-use input data must not
// displace the L2-resident accumulator that the scatter atomics hammer.
__device__ __forceinline__ float ldcs(const float* p) { return __ldcs(p); }
__device__ __forceinline__ int   ldcs(const int* p)   { return __ldcs(p); }

// One (pixel, k) pair per lane; quad-wide shuffles do the K-reduction.
// The cheap approximate-z prefilter gates the expensive exact div/exp path
// to ~26% of lanes (removing it regressed 8% — it is load-bearing).
__global__ __launch_bounds__(256) void splat_kernel(
    const int*   __restrict__ p2f,     // [N,H,W,K]
    const float* __restrict__ bary,    // [N,H,W,K,3]
    const float* __restrict__ dists,   // [N,H,W,K]
    const float* __restrict__ zbuf,    // [N,H,W,K]
    const float* __restrict__ images,  // [N,H,W,C]
    const float* __restrict__ fuv)     // [F,3,2]
{
    int t = blockIdx.x * blockDim.x + threadIdx.x;   // [0, 4*NPIX), exact grid
    int idx = t >> 2;                                // pixel
    int w = idx & (WB - 1);
    int h = (idx >> 9) & (HB - 1);
    int n = idx >> 18;

    // Coalesced per-lane loads (front-batched for MLP), streaming-hinted.
    int   fk = ldcs(p2f + t);
    float zk = ldcs(zbuf + t);
    float dk = ldcs(dists + t);
    const float* bp = bary + (size_t)t * 3;
    float b0 = ldcs(bp + 0);
    float b1 = ldcs(bp + 1);
    float b2 = ldcs(bp + 2);
    // RGB: all 4 lanes of a quad read the same 12B (L1 broadcast; bitwise
    // identical across the quad — exploited by the scatter loop below).
    float r = ldcs(images + (size_t)idx * 3 + 0);
    float g = ldcs(images + (size_t)idx * 3 + 1);
    float b = ldcs(images + (size_t)idx * 3 + 2);

    // ---- Candidate selection on CHEAP approximate z_inv ----
    // exp((z_inv - z_max)/GAMMA) is 0 whenever z_inv - z_max < -0.0105
    // (arg < -104.9 < log(min_subnormal/2)). Approximate z_inv errs
    // <= ~2.4e-7 << window slack -> candidates provably cover all nonzero
    // exps; excluded k have wnum == 0 exactly.
    const unsigned FULL = 0xffffffffu;
    const float R99 = 1.0f / 99.0f;
    bool  m  = (fk >= 0);
    float zA = m ? (100.0f - zk) * R99 : 0.0f;
    float maxA = zA;
    maxA = fmaxf(maxA, __shfl_xor_sync(FULL, maxA, 1));
    maxA = fmaxf(maxA, __shfl_xor_sync(FULL, maxA, 2));
    bool cand = m && (zA >= maxA - 0.0105f);

    // Predicated UV gather for candidates (~26% of lanes): fuv is a 3 MB
    // reused table -> default caching; latency overlaps the weight math.
    float2 u0, u1, u2;
    if (cand) {
        const float2* uvp = (const float2*)(fuv + (size_t)fk * 6);
        u0 = __ldg(uvp + 0);
        u1 = __ldg(uvp + 1);
        u2 = __ldg(uvp + 2);
    }

    // Exact z_inv (true division; its rounding IS amplified x1e4 by the exp)
    // for candidates only; exact max over candidates == exact global max.
    float ze = cand ? __fdiv_rn(__fsub_rn(100.0f, zk), 99.0f) : -1e30f;
    float zmax = ze;
    zmax = fmaxf(zmax, __shfl_xor_sync(FULL, zmax, 1));
    zmax = fmaxf(zmax, __shfl_xor_sync(FULL, zmax, 2));

    // wnum: fast-math weight path (errors here are NOT exp-amplified; the
    // only amplified step, z_inv, stays exact above).
    float wv = 0.0f;
    if (cand) {
        float e = __expf(__fmul_rn(__fsub_rn(ze, zmax), INV_GAMMA_F));
        if (e != 0.0f) {                   // argmax lane: earg==0 -> e==1
            float sarg = __fmul_rn(dk, -INV_SIGMA_F);   // -d/SIGMA
            float pr = __frcp_rn(__fadd_rn(1.0f, __expf(-sarg)));
            wv = __fmul_rn(pr, e);
        }
    }
    // Quad sum (butterfly order: <=1 ulp vs sequential; not exp-amplified).
    float s = wv;
    s = __fadd_rn(s, __shfl_xor_sync(FULL, s, 1));
    s = __fadd_rn(s, __shfl_xor_sync(FULL, s, 2));

    // ---- Per-survivor splat payload (predicated) ----
    bool alive = (wv != 0.0f);
    float wt = 0.f, ptx = 0.f, pty = 0.f;
    int pxy = 0;
    if (alive) {
        wt = __fmul_rn(wv, __frcp_rn(__fadd_rn(s, DELTA_F)));

        // Barycentric-blend UVs. Strict mul/add (no FMA) to match XLA: the
        // floor() bin below is last-ulp sensitive.
        float ux = __fadd_rn(__fadd_rn(__fmul_rn(b0, u0.x), __fmul_rn(b1, u1.x)),
                             __fmul_rn(b2, u2.x));
        float uy = __fadd_rn(__fadd_rn(__fmul_rn(b0, u0.y), __fmul_rn(b1, u1.y)),
                             __fmul_rn(b2, u2.y));

        float gx = __fadd_rn(__fmul_rn(ux, 2.0f), -1.0f);
        float gy = __fadd_rn(__fmul_rn(uy, 2.0f), -1.0f);
        float tgx = __fmul_rn(__fadd_rn(__fmul_rn(gx, 0.5f), 0.5f), 512.0f);
        float tgy = __fmul_rn(__fadd_rn(__fmul_rn(gy, 0.5f), 0.5f), 512.0f);

        // linspace(0,512,512)[i] = i*(512/511); fx = (target - lin) + coord
        const float STEP = 512.0f / 511.0f;
        float fx = __fadd_rn(__fsub_rn(tgx, __fmul_rn((float)w, STEP)), (float)w);
        float fy = __fadd_rn(__fsub_rn(tgy, __fmul_rn((float)h, STEP)), (float)h);

        float x0f = floorf(fx), y0f = floorf(fy);
        int x0 = (int)x0f, y0 = (int)y0f;
        ptx = __fsub_rn(fx, x0f);
        pty = __fsub_rn(fy, y0f);
        // x0,y0 in [-~1, 512]; pack exactly into 16-bit halves (+8 bias).
        pxy = (x0 + 8) | ((y0 + 8) << 16);
    }

    // ---- Corner redistribution: lane k of each quad handles corner k ----
    // Payload is 4 shuffles (wt, tx, ty, packed xy); r,g,b are quad-uniform
    // so corner lanes recompute r*wt locally (bitwise identical).
    int lane = threadIdx.x & 31;
    int qbase = lane & ~3;
    int dxc = lane & 1;
    int dyc = (lane >> 1) & 1;
    float4* accum_n = g_accum + ((size_t)n << 18);   // n uniform within quad

    unsigned mask = __ballot_sync(FULL, alive);
    while (mask) {
        unsigned qm = (mask >> qbase) & 0xFu;
        bool act = (qm != 0);
        int src = act ? (qbase + __ffs(qm) - 1) : lane;

        int   sp  = __shfl_sync(FULL, pxy, src);
        float swt = __shfl_sync(FULL, wt,  src);
        float stx = __shfl_sync(FULL, ptx, src);
        float sty = __shfl_sync(FULL, pty, src);

        if (act) {
            int xi = (sp & 0xffff) - 8 + dxc;
            int yi = (sp >> 16) - 8 + dyc;
            if ((unsigned)xi < (unsigned)WB && (unsigned)yi < (unsigned)HB) {
                float wx = dxc ? stx : __fsub_rn(1.0f, stx);
                float wy = dyc ? sty : __fsub_rn(1.0f, sty);
                float wgt = __fmul_rn(wx, wy);
                float4* p = accum_n + ((size_t)yi << 9) + xi;
                asm volatile(
                    "red.global.add.v4.f32 [%0], {%1, %2, %3, %4};"
                    :: "l"(p),
                       "f"(__fmul_rn(__fmul_rn(r, swt), wgt)),
                       "f"(__fmul_rn(__fmul_rn(g, swt), wgt)),
                       "f"(__fmul_rn(__fmul_rn(b, swt), wgt)),
                       "f"(__fmul_rn(swt, wgt))
                    : "memory");
            }
        }
        // Retire the processed survivor in each quad; loop for multi-survivor
        // quads (avg ~1.05 survivors -> usually a single iteration).
        alive = alive && (lane != src);
        mask = __ballot_sync(FULL, alive);
    }
}

// One pixel per thread; coalesced accumulator read (L2-hot thanks to the
// streaming-hinted splat loads), rcp, scalar contiguous stores.
__global__ __launch_bounds__(256) void finalize_kernel(float* __restrict__ out) {
    int idx = blockIdx.x * blockDim.x + threadIdx.x;   // output pixel
    int w = idx & (WB - 1);
    int h = (idx >> 9) & (HB - 1);
    int n = idx >> 18;

    // Flip H: output row h reads accumulator row (H-1-h); same w order.
    const float4* ap = &g_accum[(((size_t)n << 9) + (HB - 1 - h)) * WB + w];
    float4 a = __ldcs(ap);
    float wsum = a.w;
    float rc = __frcp_rn(fmaxf(wsum, 1e-8f));

    float* tex = out + (size_t)idx * 3;
    tex[0] = a.x * rc;
    tex[1] = a.y * rc;
    tex[2] = a.z * rc;

    float* tw = out + (size_t)NPIX * 3 + (size_t)idx * 3;
    tw[0] = wsum;
    tw[1] = wsum;
    tw[2] = wsum;
}

extern "C" void kernel_launch(void* const* d_in, const int* in_sizes, int n_in,
                              void* d_out, int out_size) {
    const int*   p2f    = (const int*)  d_in[0];
    const float* bary   = (const float*)d_in[1];
    const float* dists  = (const float*)d_in[2];
    const float* zbuf   = (const float*)d_in[3];
    const float* images = (const float*)d_in[4];
    const float* fuv    = (const float*)d_in[5];
    float* out = (float*)d_out;

    // Zero the accumulator via a memset node (copy engine; graph-capturable).
    void* accum_ptr = nullptr;
    cudaGetSymbolAddress(&accum_ptr, g_accum);
    cudaMemsetAsync(accum_ptr, 0, (size_t)NPIX * sizeof(float4), 0);

    splat_kernel<<<(NPIX * 4) / 256, 256>>>(p2f, bary, dists, zbuf, images, fuv);
    finalize_kernel<<<NPIX / 256, 256>>>(out);
}